// round 2
// baseline (speedup 1.0000x reference)
#include <cuda_runtime.h>
#include <cuda_bf16.h>

// Problem constants (match reference_code)
#define B_   256
#define V_   50257
#define U_   65536
#define M_   3

// Per-(model, batch) scale = weight[m] / sum_j exp(logits[m][b][j])
__device__ float g_scale[M_ * B_];

// ---------------------------------------------------------------------------
// Kernel 1: zero the output (d_out is poisoned 0xAA before timing)
// ---------------------------------------------------------------------------
__global__ void zero_kernel(float4* __restrict__ out, int n4) {
    int i = blockIdx.x * blockDim.x + threadIdx.x;
    if (i < n4) out[i] = make_float4(0.f, 0.f, 0.f, 0.f);
}

// ---------------------------------------------------------------------------
// Kernel 2: row sums of exp(logits) -> g_scale[m*B + b] = w[m] / sum
// grid: (B, M), block: 512 threads. Coalesced scan of one row per block.
// ---------------------------------------------------------------------------
__global__ void rowsum_kernel(const float* __restrict__ l0,
                              const float* __restrict__ l1,
                              const float* __restrict__ l2,
                              const float* __restrict__ w) {
    const int b = blockIdx.x;
    const int m = blockIdx.y;
    const float* lg = (m == 0 ? l0 : (m == 1 ? l1 : l2)) + (size_t)b * V_;

    float s = 0.f;
    for (int j = threadIdx.x; j < V_; j += blockDim.x) {
        s += __expf(lg[j]);
    }
    // warp reduce
    #pragma unroll
    for (int off = 16; off > 0; off >>= 1)
        s += __shfl_xor_sync(0xFFFFFFFFu, s, off);

    __shared__ float warp_sums[16];
    const int wid = threadIdx.x >> 5;
    const int lid = threadIdx.x & 31;
    if (lid == 0) warp_sums[wid] = s;
    __syncthreads();

    if (wid == 0) {
        const int nw = blockDim.x >> 5;
        float t = (lid < nw) ? warp_sums[lid] : 0.f;
        #pragma unroll
        for (int off = 8; off > 0; off >>= 1)
            t += __shfl_xor_sync(0xFFFFFFFFu, t, off);
        if (lid == 0) g_scale[m * B_ + b] = w[m] / t;
    }
}

// ---------------------------------------------------------------------------
// Kernel 3: scatter-add  out[b, map_m[j]] += scale[m,b] * exp(logits[m][b][j])
// grid: (ceil(V/1024), B, M), block: 256 threads, 4 strided elems per thread.
// Coalesced logits/map loads; map is tiny and L2-resident across all b.
// atomicAdd with unused return compiles to RED.E.ADD.F32 (no-return path).
// ---------------------------------------------------------------------------
__global__ void scatter_kernel(const float* __restrict__ l0,
                               const float* __restrict__ l1,
                               const float* __restrict__ l2,
                               const int*   __restrict__ m0,
                               const int*   __restrict__ m1,
                               const int*   __restrict__ m2,
                               float*       __restrict__ out) {
    const int b = blockIdx.y;
    const int m = blockIdx.z;
    const float* lg = (m == 0 ? l0 : (m == 1 ? l1 : l2)) + (size_t)b * V_;
    const int*   mp = (m == 0 ? m0 : (m == 1 ? m1 : m2));

    const float scale = g_scale[m * B_ + b];
    float* orow = out + (size_t)b * U_;

    const int base = blockIdx.x * 1024;
    #pragma unroll
    for (int k = 0; k < 4; k++) {
        const int j = base + k * 256 + threadIdx.x;
        if (j < V_) {
            const float v = __expf(lg[j]) * scale;
            atomicAdd(orow + mp[j], v);
        }
    }
}

// ---------------------------------------------------------------------------
// kernel_launch
// inputs (metadata order): logits0, logits1, logits2, map0, map1, map2, weights
// ---------------------------------------------------------------------------
extern "C" void kernel_launch(void* const* d_in, const int* in_sizes, int n_in,
                              void* d_out, int out_size) {
    const float* l0 = (const float*)d_in[0];
    const float* l1 = (const float*)d_in[1];
    const float* l2 = (const float*)d_in[2];
    const int*   m0 = (const int*)d_in[3];
    const int*   m1 = (const int*)d_in[4];
    const int*   m2 = (const int*)d_in[5];
    const float* w  = (const float*)d_in[6];
    float* out = (float*)d_out;

    // 1) zero output: B*U floats = 16,777,216 -> 4,194,304 float4
    const int n4 = (B_ * U_) / 4;
    zero_kernel<<<n4 / 256, 256>>>((float4*)out, n4);

    // 2) per-row softmax denominators
    {
        dim3 grid(B_, M_);
        rowsum_kernel<<<grid, 512>>>(l0, l1, l2, w);
    }

    // 3) weighted scatter-add
    {
        dim3 grid((V_ + 1023) / 1024, B_, M_);
        scatter_kernel<<<grid, 256>>>(l0, l1, l2, m0, m1, m2, out);
    }
}